// round 1
// baseline (speedup 1.0000x reference)
#include <cuda_runtime.h>
#include <math.h>

#define NE    32
#define DH    1024
#define DI    768
#define NT    2048
#define TOPK  8
#define NP    (NT * TOPK)   // 16384 (token, expert) pairs

// ---------------- scratch (static device globals; no runtime allocation) ---
__device__ int   g_cnt[NE];
__device__ int   g_cur[NE];
__device__ int   g_off[NE + 1];
__device__ int   g_tok[NP];          // token id per grouped position
__device__ float g_wt[NP];           // routing weight per grouped position
__device__ int   g_map[NP];          // (t*K + k) -> grouped position
__device__ float g_h[(size_t)NP * DI];   // SwiGLU intermediate (48 MB)
__device__ float g_d[(size_t)NP * DH];   // per-pair down output (64 MB)

// ---------------- setup kernels -------------------------------------------
__global__ void k_zero() {
    int i = threadIdx.x;
    if (i < NE) { g_cnt[i] = 0; g_cur[i] = 0; }
}

__global__ void k_count(const int* __restrict__ sel) {
    int i = blockIdx.x * 256 + threadIdx.x;
    if (i < NP) atomicAdd(&g_cnt[sel[i]], 1);
}

__global__ void k_scan() {
    if (threadIdx.x == 0) {
        int acc = 0;
        g_off[0] = 0;
        for (int e = 0; e < NE; e++) { acc += g_cnt[e]; g_off[e + 1] = acc; }
    }
}

__global__ void k_scatter(const int* __restrict__ sel,
                          const float* __restrict__ rw) {
    int i = blockIdx.x * 256 + threadIdx.x;
    if (i < NP) {
        int e = sel[i];
        int p = g_off[e] + atomicAdd(&g_cur[e], 1);
        g_tok[p] = i / TOPK;
        g_wt[p]  = rw[i];
        g_map[i] = p;
    }
}

// ---------------- grouped GEMM 1: gate + up + SwiGLU -----------------------
// C tile: [64 tokens x 64 I], K-dim = DH (1024), 16-deep slabs.
// 256 threads, each computes 4x4 for gate and 4x4 for up.
__global__ __launch_bounds__(256) void k_gateup(
    const float* __restrict__ hs,     // [NT, DH]
    const float* __restrict__ gate,   // [NE, DI, DH]
    const float* __restrict__ up)     // [NE, DI, DH]
{
    const int e    = blockIdx.z;
    const int base = g_off[e];
    const int cnt  = g_off[e + 1] - base;
    const int rowStart = blockIdx.y * 64;
    if (rowStart >= cnt) return;
    const int iStart = blockIdx.x * 64;

    __shared__ float As[16][64];
    __shared__ float Bg[16][64];
    __shared__ float Bu[16][64];

    const int tid = threadIdx.x;
    const int lr  = tid >> 2;        // 0..63: load row
    const int lc  = (tid & 3) * 4;   // 0,4,8,12: load col offset (float4)
    const int ty  = tid >> 4;        // 0..15
    const int tx  = tid & 15;        // 0..15

    const int grow = rowStart + lr;
    const int tok  = (grow < cnt) ? g_tok[base + grow] : -1;
    const float* ap  = hs + (size_t)((tok >= 0) ? tok : 0) * DH + lc;
    const float* bgp = gate + ((size_t)e * DI + iStart + lr) * DH + lc;
    const float* bup = up   + ((size_t)e * DI + iStart + lr) * DH + lc;

    float accg[4][4] = {}, accu[4][4] = {};

    for (int k0 = 0; k0 < DH; k0 += 16) {
        float4 av = make_float4(0.f, 0.f, 0.f, 0.f);
        if (tok >= 0) av = *(const float4*)(ap + k0);
        As[lc + 0][lr] = av.x; As[lc + 1][lr] = av.y;
        As[lc + 2][lr] = av.z; As[lc + 3][lr] = av.w;

        float4 bg4 = *(const float4*)(bgp + k0);
        Bg[lc + 0][lr] = bg4.x; Bg[lc + 1][lr] = bg4.y;
        Bg[lc + 2][lr] = bg4.z; Bg[lc + 3][lr] = bg4.w;

        float4 bu4 = *(const float4*)(bup + k0);
        Bu[lc + 0][lr] = bu4.x; Bu[lc + 1][lr] = bu4.y;
        Bu[lc + 2][lr] = bu4.z; Bu[lc + 3][lr] = bu4.w;

        __syncthreads();

        #pragma unroll
        for (int kk = 0; kk < 16; kk++) {
            float4 a4 = *(const float4*)&As[kk][ty * 4];
            float4 g4 = *(const float4*)&Bg[kk][tx * 4];
            float4 u4 = *(const float4*)&Bu[kk][tx * 4];
            float ar[4] = {a4.x, a4.y, a4.z, a4.w};
            float gr[4] = {g4.x, g4.y, g4.z, g4.w};
            float ur[4] = {u4.x, u4.y, u4.z, u4.w};
            #pragma unroll
            for (int i = 0; i < 4; i++)
                #pragma unroll
                for (int j = 0; j < 4; j++) {
                    accg[i][j] += ar[i] * gr[j];
                    accu[i][j] += ar[i] * ur[j];
                }
        }
        __syncthreads();
    }

    // epilogue: h = w * silu(g) * u
    #pragma unroll
    for (int i = 0; i < 4; i++) {
        int r = rowStart + ty * 4 + i;
        if (r < cnt) {
            float w = g_wt[base + r];
            float* hp = &g_h[(size_t)(base + r) * DI + iStart + tx * 4];
            #pragma unroll
            for (int j = 0; j < 4; j++) {
                float gv = accg[i][j];
                float sg = gv / (1.f + __expf(-gv));
                hp[j] = w * sg * accu[i][j];
            }
        }
    }
}

// ---------------- grouped GEMM 2: down projection --------------------------
// C tile: [64 tokens x 64 H], K-dim = DI (768).
__global__ __launch_bounds__(256) void k_down(
    const float* __restrict__ down)   // [NE, DH, DI]
{
    const int e    = blockIdx.z;
    const int base = g_off[e];
    const int cnt  = g_off[e + 1] - base;
    const int rowStart = blockIdx.y * 64;
    if (rowStart >= cnt) return;
    const int hStart = blockIdx.x * 64;

    __shared__ float As[16][64];
    __shared__ float Bs[16][64];

    const int tid = threadIdx.x;
    const int lr  = tid >> 2;
    const int lc  = (tid & 3) * 4;
    const int ty  = tid >> 4;
    const int tx  = tid & 15;

    const int grow  = rowStart + lr;
    const bool arow = (grow < cnt);
    const float* ap = g_h + (size_t)(base + (arow ? grow : 0)) * DI + lc;
    const float* bp = down + ((size_t)e * DH + hStart + lr) * DI + lc;

    float acc[4][4] = {};

    for (int k0 = 0; k0 < DI; k0 += 16) {
        float4 av = make_float4(0.f, 0.f, 0.f, 0.f);
        if (arow) av = *(const float4*)(ap + k0);
        As[lc + 0][lr] = av.x; As[lc + 1][lr] = av.y;
        As[lc + 2][lr] = av.z; As[lc + 3][lr] = av.w;

        float4 bv = *(const float4*)(bp + k0);
        Bs[lc + 0][lr] = bv.x; Bs[lc + 1][lr] = bv.y;
        Bs[lc + 2][lr] = bv.z; Bs[lc + 3][lr] = bv.w;

        __syncthreads();

        #pragma unroll
        for (int kk = 0; kk < 16; kk++) {
            float4 a4 = *(const float4*)&As[kk][ty * 4];
            float4 b4 = *(const float4*)&Bs[kk][tx * 4];
            float ar[4] = {a4.x, a4.y, a4.z, a4.w};
            float br[4] = {b4.x, b4.y, b4.z, b4.w};
            #pragma unroll
            for (int i = 0; i < 4; i++)
                #pragma unroll
                for (int j = 0; j < 4; j++)
                    acc[i][j] += ar[i] * br[j];
        }
        __syncthreads();
    }

    #pragma unroll
    for (int i = 0; i < 4; i++) {
        int r = rowStart + ty * 4 + i;
        if (r < cnt) {
            float* dp = &g_d[(size_t)(base + r) * DH + hStart + tx * 4];
            #pragma unroll
            for (int j = 0; j < 4; j++) dp[j] = acc[i][j];
        }
    }
}

// ---------------- deterministic combine ------------------------------------
// out[t, :] = sum_k g_d[pos(t,k), :]   (routing weight already folded into h)
__global__ void k_combine(float* __restrict__ out) {
    const int t = blockIdx.x;
    __shared__ int ps[TOPK];
    if (threadIdx.x < TOPK) ps[threadIdx.x] = g_map[t * TOPK + threadIdx.x];
    __syncthreads();
    const int h = threadIdx.x * 4;   // 256 threads * float4 = 1024 = DH
    float4 s = make_float4(0.f, 0.f, 0.f, 0.f);
    #pragma unroll
    for (int k = 0; k < TOPK; k++) {
        float4 v = *(const float4*)&g_d[(size_t)ps[k] * DH + h];
        s.x += v.x; s.y += v.y; s.z += v.z; s.w += v.w;
    }
    *(float4*)&out[(size_t)t * DH + h] = s;
}

// ---------------- launch ----------------------------------------------------
extern "C" void kernel_launch(void* const* d_in, const int* in_sizes, int n_in,
                              void* d_out, int out_size) {
    const float* hs   = (const float*)d_in[0];   // [T, H]
    const float* rw   = (const float*)d_in[1];   // [T, K]
    const int*   sel  = (const int*)  d_in[2];   // [T, K]
    const float* gate = (const float*)d_in[3];   // [E, I, H]
    const float* up   = (const float*)d_in[4];   // [E, I, H]
    const float* down = (const float*)d_in[5];   // [E, H, I]
    float* out = (float*)d_out;                  // [T, H]

    k_zero<<<1, 32>>>();
    k_count<<<(NP + 255) / 256, 256>>>(sel);
    k_scan<<<1, 1>>>();
    k_scatter<<<(NP + 255) / 256, 256>>>(sel, rw);

    dim3 g4(DI / 64, NP / 64, NE);   // (12, 256, 32) — early-exit on token tiles
    k_gateup<<<g4, 256>>>(hs, gate, up);

    dim3 g5(DH / 64, NP / 64, NE);   // (16, 256, 32)
    k_down<<<g5, 256>>>(down);

    k_combine<<<NT, 256>>>(out);
}

// round 3
// speedup vs baseline: 2.5144x; 2.5144x over previous
#include <cuda_runtime.h>
#include <cuda_bf16.h>
#include <stdint.h>
#include <math.h>

#define NE    32
#define DH    1024
#define DI    768
#define NT    2048
#define TOPK  8
#define NP    (NT * TOPK)   // 16384 (token, expert) pairs
#define KC    64            // K elems per chunk (64 bf16 = 128 B = SW128 row)

// tcgen05 only exists on the arch-specific ('a') compilation pass.
#if defined(__CUDA_ARCH__) && defined(__CUDA_ARCH_FEAT_SM103_ALL)
#define TC 1
#else
#define TC 0
#endif

// ---------------- scratch (static device globals) ---------------------------
__device__ int   g_cnt[NE];
__device__ int   g_cur[NE];
__device__ int   g_off[NE + 1];
__device__ int   g_tok[NP];
__device__ float g_wt[NP];
__device__ int   g_map[NP];
__device__ __align__(16) __nv_bfloat16 g_h_hi[(size_t)NP * DI];
__device__ __align__(16) __nv_bfloat16 g_h_lo[(size_t)NP * DI];
__device__ __align__(16) float         g_d[(size_t)NP * DH];

// ---------------- common helpers ---------------------------------------------
#define SWZ(o) ((o) ^ (((o) >> 3) & 0x70))

__device__ __forceinline__ uint32_t smem_u32(const void* p) {
    uint32_t a;
    asm("{ .reg .u64 t; cvta.to.shared.u64 t, %1; cvt.u32.u64 %0, t; }"
        : "=r"(a) : "l"(p));
    return a;
}

__device__ __forceinline__ void split1(float v, uint16_t* h, uint16_t* l) {
    __nv_bfloat16 hb = __float2bfloat16_rn(v);
    *h = __bfloat16_as_ushort(hb);
    *l = __bfloat16_as_ushort(__float2bfloat16_rn(v - __bfloat162float(hb)));
}

// Fill one 128x64 bf16 smem tile pair (hi/lo) from fp32 global rows.
__device__ __forceinline__ void fill_f32_tile(char* th, char* tl,
        const float* rowp, int k0, int frow, int fcol, bool valid) {
    #pragma unroll
    for (int j = 0; j < 4; j++) {
        float v[8];
        if (valid) {
            float4 a0 = *(const float4*)(rowp + k0 + fcol + j * 8);
            float4 a1 = *(const float4*)(rowp + k0 + fcol + j * 8 + 4);
            v[0] = a0.x; v[1] = a0.y; v[2] = a0.z; v[3] = a0.w;
            v[4] = a1.x; v[5] = a1.y; v[6] = a1.z; v[7] = a1.w;
        } else {
            #pragma unroll
            for (int q = 0; q < 8; q++) v[q] = 0.f;
        }
        uint16_t hh[8], ll[8];
        #pragma unroll
        for (int q = 0; q < 8; q++) split1(v[q], &hh[q], &ll[q]);
        uint4 vh, vl;
        vh.x = hh[0] | ((uint32_t)hh[1] << 16); vh.y = hh[2] | ((uint32_t)hh[3] << 16);
        vh.z = hh[4] | ((uint32_t)hh[5] << 16); vh.w = hh[6] | ((uint32_t)hh[7] << 16);
        vl.x = ll[0] | ((uint32_t)ll[1] << 16); vl.y = ll[2] | ((uint32_t)ll[3] << 16);
        vl.z = ll[4] | ((uint32_t)ll[5] << 16); vl.w = ll[6] | ((uint32_t)ll[7] << 16);
        uint32_t s = SWZ((uint32_t)(frow * 128 + fcol * 2 + j * 16));
        *(uint4*)(th + s) = vh;
        *(uint4*)(tl + s) = vl;
    }
}

// Fill one 128x64 bf16 smem tile pair from pre-split bf16 global rows.
__device__ __forceinline__ void fill_b16_tile(char* th, char* tl,
        const __nv_bfloat16* ph, const __nv_bfloat16* pl,
        int k0, int frow, int fcol, bool valid) {
    #pragma unroll
    for (int j = 0; j < 4; j++) {
        uint4 vh = make_uint4(0, 0, 0, 0), vl = make_uint4(0, 0, 0, 0);
        if (valid) {
            vh = *(const uint4*)(ph + k0 + fcol + j * 8);
            vl = *(const uint4*)(pl + k0 + fcol + j * 8);
        }
        uint32_t s = SWZ((uint32_t)(frow * 128 + fcol * 2 + j * 16));
        *(uint4*)(th + s) = vh;
        *(uint4*)(tl + s) = vl;
    }
}

#if TC
// ---------------- tcgen05 helpers (sm_103a pass only) -------------------------
__device__ __forceinline__ uint32_t elect1() {
    uint32_t p;
    asm volatile("{\n\t.reg .pred p;\n\telect.sync _|p, 0xFFFFFFFF;\n\t"
                 "selp.b32 %0,1,0,p;\n\t}" : "=r"(p));
    return p;
}

__device__ __forceinline__ void mma_f16_ss(uint32_t d, uint64_t a, uint64_t b,
                                           uint32_t idesc, uint32_t en) {
    asm volatile("{\n\t.reg .pred p;\n\tsetp.ne.u32 p, %4, 0;\n\t"
        "tcgen05.mma.cta_group::1.kind::f16 [%0], %1, %2, %3, {%5,%5,%5,%5}, p;\n\t}"
        :: "r"(d), "l"(a), "l"(b), "r"(idesc), "r"(en), "r"(0u) : "memory");
}

static constexpr uint64_t DESC_BASE =
    (2ULL << 61) | (1ULL << 46) | (64ULL << 32) | (1ULL << 16);  // SW128 K-major
__device__ __forceinline__ uint64_t mkdesc(uint32_t addr) {
    return DESC_BASE | ((uint64_t)(addr >> 4) & 0x3FFF);
}

// idesc: dtype=F32, atype=btype=BF16, N=128, M=128
#define IDESC ((1u << 4) | (1u << 7) | (1u << 10) | (16u << 17) | (8u << 24))

#define MBAR_INIT(a, c) \
    asm volatile("mbarrier.init.shared.b64 [%0], %1;" :: "r"(a), "r"(c) : "memory")
#define MBAR_INVAL(a) \
    asm volatile("mbarrier.inval.shared.b64 [%0];" :: "r"(a) : "memory")
#define TM_COMMIT(a) \
    asm volatile("tcgen05.commit.cta_group::1.mbarrier::arrive::one.shared::cluster.b64 [%0];" \
                 :: "r"(a) : "memory")
#define TM_WAIT_LD()      asm volatile("tcgen05.wait::ld.sync.aligned;" ::: "memory")
#define TM_FENCE_AFTER()  asm volatile("tcgen05.fence::after_thread_sync;" ::: "memory")
#define TM_FENCE_BEFORE() asm volatile("tcgen05.fence::before_thread_sync;" ::: "memory")

#define MBAR_WAIT(mbar_addr, ph) do { \
    uint32_t _m = (mbar_addr); uint32_t _p = (ph); uint32_t _done; \
    asm volatile("{\n\t.reg .pred p;\n\t" \
        "mbarrier.try_wait.parity.acquire.cta.shared::cta.b64 p, [%1], %2;\n\t" \
        "selp.b32 %0, 1, 0, p;\n\t}" : "=r"(_done) : "r"(_m), "r"(_p) : "memory"); \
    if (!_done) { \
        asm volatile("{\n\t.reg .pred P1;\n\t" \
            "WL_%=:\n\t" \
            "mbarrier.try_wait.parity.acquire.cta.shared::cta.b64 P1, [%0], %1, 0x989680;\n\t" \
            "@P1 bra.uni WD_%=;\n\tbra.uni WL_%=;\n\tWD_%=:\n\t}" \
            :: "r"(_m), "r"(_p) : "memory"); \
    } \
} while (0)

__device__ __forceinline__ void ldtm32(uint32_t* r, uint32_t a) {
    asm volatile("tcgen05.ld.sync.aligned.32x32b.x32.b32 "
        "{%0, %1, %2, %3, %4, %5, %6, %7, %8, %9, %10, %11, %12, %13, %14, %15, "
        "%16, %17, %18, %19, %20, %21, %22, %23, %24, %25, %26, %27, %28, %29, %30, %31}, [%32];"
        : "=r"(r[0]),  "=r"(r[1]),  "=r"(r[2]),  "=r"(r[3]),
          "=r"(r[4]),  "=r"(r[5]),  "=r"(r[6]),  "=r"(r[7]),
          "=r"(r[8]),  "=r"(r[9]),  "=r"(r[10]), "=r"(r[11]),
          "=r"(r[12]), "=r"(r[13]), "=r"(r[14]), "=r"(r[15]),
          "=r"(r[16]), "=r"(r[17]), "=r"(r[18]), "=r"(r[19]),
          "=r"(r[20]), "=r"(r[21]), "=r"(r[22]), "=r"(r[23]),
          "=r"(r[24]), "=r"(r[25]), "=r"(r[26]), "=r"(r[27]),
          "=r"(r[28]), "=r"(r[29]), "=r"(r[30]), "=r"(r[31])
        : "r"(a));
}
#else
// ---------------- HMMA fallback helpers (plain sm_103 pass) -------------------
__device__ __forceinline__ void ldm4(uint32_t* r, uint32_t a) {
    asm volatile("ldmatrix.sync.aligned.m8n8.x4.shared.b16 {%0,%1,%2,%3}, [%4];"
        : "=r"(r[0]), "=r"(r[1]), "=r"(r[2]), "=r"(r[3]) : "r"(a));
}
__device__ __forceinline__ void mma_bf(float* d, const uint32_t* a, const uint32_t* b) {
    asm volatile("mma.sync.aligned.m16n8k16.row.col.f32.bf16.bf16.f32 "
        "{%0,%1,%2,%3}, {%4,%5,%6,%7}, {%8,%9}, {%0,%1,%2,%3};"
        : "+f"(d[0]), "+f"(d[1]), "+f"(d[2]), "+f"(d[3])
        : "r"(a[0]), "r"(a[1]), "r"(a[2]), "r"(a[3]), "r"(b[0]), "r"(b[1]));
}
#endif

// ---------------- setup kernels ----------------------------------------------
__global__ void k_zero() {
    int i = threadIdx.x;
    if (i < NE) { g_cnt[i] = 0; g_cur[i] = 0; }
}
__global__ void k_count(const int* __restrict__ sel) {
    int i = blockIdx.x * 256 + threadIdx.x;
    if (i < NP) atomicAdd(&g_cnt[sel[i]], 1);
}
__global__ void k_scan() {
    if (threadIdx.x == 0) {
        int acc = 0; g_off[0] = 0;
        for (int e = 0; e < NE; e++) { acc += g_cnt[e]; g_off[e + 1] = acc; }
    }
}
__global__ void k_scatter(const int* __restrict__ sel, const float* __restrict__ rw) {
    int i = blockIdx.x * 256 + threadIdx.x;
    if (i < NP) {
        int e = sel[i];
        int p = g_off[e] + atomicAdd(&g_cur[e], 1);
        g_tok[p] = i / TOPK;
        g_wt[p]  = rw[i];
        g_map[i] = p;
    }
}

// ---------------- GEMM 1: gate + up, SwiGLU epilogue --------------------------
#define GU_SMEM (6 * 16384 + 1024 + 64)

__global__ __launch_bounds__(256) __cluster_dims__(1, 1, 1)
void k_gateup(const float* __restrict__ hs, const float* __restrict__ gate,
              const float* __restrict__ up) {
    const int e    = blockIdx.z;
    const int base = g_off[e];
    const int cnt  = g_off[e + 1] - base;
    const int rowStart = blockIdx.y * 128;
    if (rowStart >= cnt) return;
    const int iStart = blockIdx.x * 128;

    extern __shared__ char raw[];
    char* sm = (char*)(((uintptr_t)raw + 1023) & ~(uintptr_t)1023);
    char* A_hi = sm;
    char* A_lo = sm + 16384;
    char* G_hi = sm + 32768;
    char* G_lo = sm + 49152;
    char* U_hi = sm + 65536;
    char* U_lo = sm + 81920;

    const int tid = threadIdx.x;
    const int wid = tid >> 5, lane = tid & 31;
    const int frow = tid >> 1, fcol = (tid & 1) * 32;

    const int grow = rowStart + frow;
    const bool av  = (grow < cnt);
    const int tok  = av ? g_tok[base + grow] : 0;
    const float* ap  = hs + (size_t)tok * DH;
    const float* gp  = gate + ((size_t)e * DI + iStart + frow) * DH;
    const float* upp = up   + ((size_t)e * DI + iStart + frow) * DH;

#if TC
    uint32_t tmp_addr = smem_u32(sm + 98304);
    uint32_t mbar     = smem_u32(sm + 98304 + 16);
    if (wid == 0) {
        asm volatile("tcgen05.alloc.cta_group::1.sync.aligned.shared::cta.b32 [%0], %1;"
                     :: "r"(tmp_addr), "r"(256) : "memory");
        asm volatile("tcgen05.relinquish_alloc_permit.cta_group::1.sync.aligned;");
    }
    if (tid == 0) MBAR_INIT(mbar, 1);
    __syncthreads();
    uint32_t tmem;
    asm volatile("ld.shared.b32 %0, [%1];" : "=r"(tmem) : "r"(tmp_addr));

    const uint64_t dAh = mkdesc(smem_u32(A_hi)), dAl = mkdesc(smem_u32(A_lo));
    const uint64_t dGh = mkdesc(smem_u32(G_hi)), dGl = mkdesc(smem_u32(G_lo));
    const uint64_t dUh = mkdesc(smem_u32(U_hi)), dUl = mkdesc(smem_u32(U_lo));

    for (int c = 0; c < DH / KC; c++) {
        const int k0 = c * KC;
        fill_f32_tile(A_hi, A_lo, ap,  k0, frow, fcol, av);
        fill_f32_tile(G_hi, G_lo, gp,  k0, frow, fcol, true);
        fill_f32_tile(U_hi, U_lo, upp, k0, frow, fcol, true);
        asm volatile("fence.proxy.async.shared::cta;" ::: "memory");
        __syncthreads();
        if (wid == 0 && elect1()) {
            #pragma unroll
            for (int ks = 0; ks < 4; ks++) {
                uint32_t en0 = (c | ks) ? 1u : 0u;
                mma_f16_ss(tmem,       dAh + ks * 2, dGh + ks * 2, IDESC, en0);
                mma_f16_ss(tmem,       dAh + ks * 2, dGl + ks * 2, IDESC, 1u);
                mma_f16_ss(tmem,       dAl + ks * 2, dGh + ks * 2, IDESC, 1u);
                mma_f16_ss(tmem + 128, dAh + ks * 2, dUh + ks * 2, IDESC, en0);
                mma_f16_ss(tmem + 128, dAh + ks * 2, dUl + ks * 2, IDESC, 1u);
                mma_f16_ss(tmem + 128, dAl + ks * 2, dUh + ks * 2, IDESC, 1u);
            }
            TM_COMMIT(mbar);
        }
        MBAR_WAIT(mbar, c & 1);
    }

    TM_FENCE_AFTER();
    const int r = rowStart + (wid & 3) * 32 + lane;
    const bool valid = (r < cnt);
    const float w = valid ? g_wt[base + r] : 0.f;
    const int colBase = (wid >> 2) * 64;
    const size_t rb = (size_t)(valid ? base + r : 0) * DI + iStart;

    #pragma unroll
    for (int cg = 0; cg < 2; cg++) {
        const int cb = colBase + cg * 32;
        uint32_t gr[32], ur[32];
        ldtm32(gr, tmem + cb);
        ldtm32(ur, tmem + 128 + cb);
        TM_WAIT_LD();
        if (valid) {
            #pragma unroll
            for (int u4i = 0; u4i < 4; u4i++) {
                uint32_t hw[4], lw[4];
                #pragma unroll
                for (int p = 0; p < 4; p++) {
                    int j = u4i * 8 + p * 2;
                    float g0 = __uint_as_float(gr[j]),   g1 = __uint_as_float(gr[j + 1]);
                    float u0 = __uint_as_float(ur[j]),   u1 = __uint_as_float(ur[j + 1]);
                    float h0 = w * (g0 / (1.f + __expf(-g0))) * u0;
                    float h1 = w * (g1 / (1.f + __expf(-g1))) * u1;
                    uint16_t a0, b0, a1, b1;
                    split1(h0, &a0, &b0); split1(h1, &a1, &b1);
                    hw[p] = a0 | ((uint32_t)a1 << 16);
                    lw[p] = b0 | ((uint32_t)b1 << 16);
                }
                *(uint4*)&g_h_hi[rb + cb + u4i * 8] = make_uint4(hw[0], hw[1], hw[2], hw[3]);
                *(uint4*)&g_h_lo[rb + cb + u4i * 8] = make_uint4(lw[0], lw[1], lw[2], lw[3]);
            }
        }
    }
    TM_FENCE_BEFORE();
    __syncthreads();
    if (tid == 0) MBAR_INVAL(mbar);
    __syncthreads();
    if (wid == 0)
        asm volatile("tcgen05.dealloc.cta_group::1.sync.aligned.b32 %0, %1;"
                     :: "r"(tmem), "r"(256));
#else
    const uint32_t sAh = smem_u32(A_hi), sAl = smem_u32(A_lo);
    const uint32_t sGh = smem_u32(G_hi), sGl = smem_u32(G_lo);
    const uint32_t sUh = smem_u32(U_hi), sUl = smem_u32(U_lo);
    const int wm = wid & 3, wn = wid >> 2;
    float accg[2][8][4], accu[2][8][4];
    #pragma unroll
    for (int a = 0; a < 2; a++)
        #pragma unroll
        for (int b = 0; b < 8; b++)
            #pragma unroll
            for (int q = 0; q < 4; q++) { accg[a][b][q] = 0.f; accu[a][b][q] = 0.f; }

    const int a_r = (lane & 15);
    const int a_k = (lane >> 4) * 16;
    const int b_r = ((lane >> 4) & 1) * 8 + (lane & 7);
    const int b_k = ((lane >> 3) & 1) * 16;

    for (int c = 0; c < DH / KC; c++) {
        const int k0 = c * KC;
        fill_f32_tile(A_hi, A_lo, ap,  k0, frow, fcol, av);
        fill_f32_tile(G_hi, G_lo, gp,  k0, frow, fcol, true);
        fill_f32_tile(U_hi, U_lo, upp, k0, frow, fcol, true);
        __syncthreads();
        #pragma unroll
        for (int ks = 0; ks < 4; ks++) {
            uint32_t ah[2][4], al[2][4];
            #pragma unroll
            for (int mi = 0; mi < 2; mi++) {
                uint32_t off = SWZ((uint32_t)((wm * 32 + mi * 16 + a_r) * 128 + ks * 32 + a_k));
                ldm4(ah[mi], sAh + off);
                ldm4(al[mi], sAl + off);
            }
            #pragma unroll
            for (int njp = 0; njp < 4; njp++) {
                uint32_t boff = SWZ((uint32_t)((wn * 64 + njp * 16 + b_r) * 128 + ks * 32 + b_k));
                uint32_t bh[4], bl[4];
                ldm4(bh, sGh + boff);
                ldm4(bl, sGl + boff);
                #pragma unroll
                for (int mi = 0; mi < 2; mi++)
                    #pragma unroll
                    for (int j = 0; j < 2; j++) {
                        mma_bf(accg[mi][njp * 2 + j], ah[mi], &bh[j * 2]);
                        mma_bf(accg[mi][njp * 2 + j], ah[mi], &bl[j * 2]);
                        mma_bf(accg[mi][njp * 2 + j], al[mi], &bh[j * 2]);
                    }
                ldm4(bh, sUh + boff);
                ldm4(bl, sUl + boff);
                #pragma unroll
                for (int mi = 0; mi < 2; mi++)
                    #pragma unroll
                    for (int j = 0; j < 2; j++) {
                        mma_bf(accu[mi][njp * 2 + j], ah[mi], &bh[j * 2]);
                        mma_bf(accu[mi][njp * 2 + j], ah[mi], &bl[j * 2]);
                        mma_bf(accu[mi][njp * 2 + j], al[mi], &bh[j * 2]);
                    }
            }
        }
        __syncthreads();
    }

    #pragma unroll
    for (int mi = 0; mi < 2; mi++) {
        #pragma unroll
        for (int h2 = 0; h2 < 2; h2++) {
            const int r = rowStart + wm * 32 + mi * 16 + (lane >> 2) + h2 * 8;
            if (r < cnt) {
                const float w = g_wt[base + r];
                const size_t rb = (size_t)(base + r) * DI + iStart;
                #pragma unroll
                for (int nj = 0; nj < 8; nj++) {
                    const int col = wn * 64 + nj * 8 + (lane & 3) * 2;
                    float g0 = accg[mi][nj][h2 * 2 + 0], g1 = accg[mi][nj][h2 * 2 + 1];
                    float u0 = accu[mi][nj][h2 * 2 + 0], u1 = accu[mi][nj][h2 * 2 + 1];
                    float h0 = w * (g0 / (1.f + __expf(-g0))) * u0;
                    float h1 = w * (g1 / (1.f + __expf(-g1))) * u1;
                    uint16_t a0, b0, a1, b1;
                    split1(h0, &a0, &b0); split1(h1, &a1, &b1);
                    *(uint32_t*)&g_h_hi[rb + col] = a0 | ((uint32_t)a1 << 16);
                    *(uint32_t*)&g_h_lo[rb + col] = b0 | ((uint32_t)b1 << 16);
                }
            }
        }
    }
#endif
}

// ---------------- GEMM 2: down projection -> g_d ------------------------------
#define DN_SMEM (4 * 16384 + 1024 + 64)

__global__ __launch_bounds__(256) __cluster_dims__(1, 1, 1)
void k_down(const float* __restrict__ down) {
    const int e    = blockIdx.z;
    const int base = g_off[e];
    const int cnt  = g_off[e + 1] - base;
    const int rowStart = blockIdx.y * 128;
    if (rowStart >= cnt) return;
    const int hStart = blockIdx.x * 128;

    extern __shared__ char raw[];
    char* sm = (char*)(((uintptr_t)raw + 1023) & ~(uintptr_t)1023);
    char* A_hi = sm;
    char* A_lo = sm + 16384;
    char* B_hi = sm + 32768;
    char* B_lo = sm + 49152;

    const int tid = threadIdx.x;
    const int wid = tid >> 5, lane = tid & 31;
    const int frow = tid >> 1, fcol = (tid & 1) * 32;

    const int grow = rowStart + frow;
    const bool av  = (grow < cnt);
    const __nv_bfloat16* ah = g_h_hi + (size_t)(av ? base + grow : 0) * DI;
    const __nv_bfloat16* al = g_h_lo + (size_t)(av ? base + grow : 0) * DI;
    const float* bp = down + ((size_t)e * DH + hStart + frow) * DI;

#if TC
    uint32_t tmp_addr = smem_u32(sm + 65536);
    uint32_t mbar     = smem_u32(sm + 65536 + 16);
    if (wid == 0) {
        asm volatile("tcgen05.alloc.cta_group::1.sync.aligned.shared::cta.b32 [%0], %1;"
                     :: "r"(tmp_addr), "r"(128) : "memory");
        asm volatile("tcgen05.relinquish_alloc_permit.cta_group::1.sync.aligned;");
    }
    if (tid == 0) MBAR_INIT(mbar, 1);
    __syncthreads();
    uint32_t tmem;
    asm volatile("ld.shared.b32 %0, [%1];" : "=r"(tmem) : "r"(tmp_addr));

    const uint64_t dAh = mkdesc(smem_u32(A_hi)), dAl = mkdesc(smem_u32(A_lo));
    const uint64_t dBh = mkdesc(smem_u32(B_hi)), dBl = mkdesc(smem_u32(B_lo));

    for (int c = 0; c < DI / KC; c++) {
        const int k0 = c * KC;
        fill_b16_tile(A_hi, A_lo, ah, al, k0, frow, fcol, av);
        fill_f32_tile(B_hi, B_lo, bp, k0, frow, fcol, true);
        asm volatile("fence.proxy.async.shared::cta;" ::: "memory");
        __syncthreads();
        if (wid == 0 && elect1()) {
            #pragma unroll
            for (int ks = 0; ks < 4; ks++) {
                uint32_t en0 = (c | ks) ? 1u : 0u;
                mma_f16_ss(tmem, dAh + ks * 2, dBh + ks * 2, IDESC, en0);
                mma_f16_ss(tmem, dAh + ks * 2, dBl + ks * 2, IDESC, 1u);
                mma_f16_ss(tmem, dAl + ks * 2, dBh + ks * 2, IDESC, 1u);
            }
            TM_COMMIT(mbar);
        }
        MBAR_WAIT(mbar, c & 1);
    }

    TM_FENCE_AFTER();
    const int r = rowStart + (wid & 3) * 32 + lane;
    const bool valid = (r < cnt);
    const int colBase = (wid >> 2) * 64;
    float* dp = &g_d[(size_t)(valid ? base + r : 0) * DH + hStart];

    #pragma unroll
    for (int cg = 0; cg < 2; cg++) {
        const int cb = colBase + cg * 32;
        uint32_t dr[32];
        ldtm32(dr, tmem + cb);
        TM_WAIT_LD();
        if (valid) {
            #pragma unroll
            for (int q = 0; q < 8; q++) {
                float4 o;
                o.x = __uint_as_float(dr[q * 4 + 0]);
                o.y = __uint_as_float(dr[q * 4 + 1]);
                o.z = __uint_as_float(dr[q * 4 + 2]);
                o.w = __uint_as_float(dr[q * 4 + 3]);
                *(float4*)(dp + cb + q * 4) = o;
            }
        }
    }
    TM_FENCE_BEFORE();
    __syncthreads();
    if (tid == 0) MBAR_INVAL(mbar);
    __syncthreads();
    if (wid == 0)
        asm volatile("tcgen05.dealloc.cta_group::1.sync.aligned.b32 %0, %1;"
                     :: "r"(tmem), "r"(128));
#else
    const uint32_t sAh = smem_u32(A_hi), sAl = smem_u32(A_lo);
    const uint32_t sBh = smem_u32(B_hi), sBl = smem_u32(B_lo);
    const int wm = wid & 3, wn = wid >> 2;
    float acc[2][8][4];
    #pragma unroll
    for (int a = 0; a < 2; a++)
        #pragma unroll
        for (int b = 0; b < 8; b++)
            #pragma unroll
            for (int q = 0; q < 4; q++) acc[a][b][q] = 0.f;

    const int a_r = (lane & 15);
    const int a_k = (lane >> 4) * 16;
    const int b_r = ((lane >> 4) & 1) * 8 + (lane & 7);
    const int b_k = ((lane >> 3) & 1) * 16;

    for (int c = 0; c < DI / KC; c++) {
        const int k0 = c * KC;
        fill_b16_tile(A_hi, A_lo, ah, al, k0, frow, fcol, av);
        fill_f32_tile(B_hi, B_lo, bp, k0, frow, fcol, true);
        __syncthreads();
        #pragma unroll
        for (int ks = 0; ks < 4; ks++) {
            uint32_t ahf[2][4], alf[2][4];
            #pragma unroll
            for (int mi = 0; mi < 2; mi++) {
                uint32_t off = SWZ((uint32_t)((wm * 32 + mi * 16 + a_r) * 128 + ks * 32 + a_k));
                ldm4(ahf[mi], sAh + off);
                ldm4(alf[mi], sAl + off);
            }
            #pragma unroll
            for (int njp = 0; njp < 4; njp++) {
                uint32_t boff = SWZ((uint32_t)((wn * 64 + njp * 16 + b_r) * 128 + ks * 32 + b_k));
                uint32_t bh[4], bl[4];
                ldm4(bh, sBh + boff);
                ldm4(bl, sBl + boff);
                #pragma unroll
                for (int mi = 0; mi < 2; mi++)
                    #pragma unroll
                    for (int j = 0; j < 2; j++) {
                        mma_bf(acc[mi][njp * 2 + j], ahf[mi], &bh[j * 2]);
                        mma_bf(acc[mi][njp * 2 + j], ahf[mi], &bl[j * 2]);
                        mma_bf(acc[mi][njp * 2 + j], alf[mi], &bh[j * 2]);
                    }
            }
        }
        __syncthreads();
    }

    #pragma unroll
    for (int mi = 0; mi < 2; mi++) {
        #pragma unroll
        for (int h2 = 0; h2 < 2; h2++) {
            const int r = rowStart + wm * 32 + mi * 16 + (lane >> 2) + h2 * 8;
            if (r < cnt) {
                float* dp = &g_d[(size_t)(base + r) * DH + hStart];
                #pragma unroll
                for (int nj = 0; nj < 8; nj++) {
                    const int col = wn * 64 + nj * 8 + (lane & 3) * 2;
                    float2 o;
                    o.x = acc[mi][nj][h2 * 2 + 0];
                    o.y = acc[mi][nj][h2 * 2 + 1];
                    *(float2*)(dp + col) = o;
                }
            }
        }
    }
#endif
}

// ---------------- deterministic combine ---------------------------------------
__global__ void k_combine(float* __restrict__ out) {
    const int t = blockIdx.x;
    __shared__ int ps[TOPK];
    if (threadIdx.x < TOPK) ps[threadIdx.x] = g_map[t * TOPK + threadIdx.x];
    __syncthreads();
    const int h = threadIdx.x * 4;
    float4 s = make_float4(0.f, 0.f, 0.f, 0.f);
    #pragma unroll
    for (int k = 0; k < TOPK; k++) {
        float4 v = *(const float4*)&g_d[(size_t)ps[k] * DH + h];
        s.x += v.x; s.y += v.y; s.z += v.z; s.w += v.w;
    }
    *(float4*)&out[(size_t)t * DH + h] = s;
}

// ---------------- launch -------------------------------------------------------
extern "C" void kernel_launch(void* const* d_in, const int* in_sizes, int n_in,
                              void* d_out, int out_size) {
    const float* hs   = (const float*)d_in[0];
    const float* rw   = (const float*)d_in[1];
    const int*   sel  = (const int*)  d_in[2];
    const float* gate = (const float*)d_in[3];
    const float* up   = (const float*)d_in[4];
    const float* down = (const float*)d_in[5];
    float* out = (float*)d_out;

    k_zero<<<1, 32>>>();
    k_count<<<(NP + 255) / 256, 256>>>(sel);
    k_scan<<<1, 1>>>();
    k_scatter<<<(NP + 255) / 256, 256>>>(sel, rw);

    cudaFuncSetAttribute(k_gateup, cudaFuncAttributeMaxDynamicSharedMemorySize, GU_SMEM);
    cudaFuncSetAttribute(k_down,   cudaFuncAttributeMaxDynamicSharedMemorySize, DN_SMEM);

    // 16 token-tiles per expert covers cnt <= 2048 (expected 512, sigma ~22)
    dim3 gg(DI / 128, 16, NE);   // (6, 16, 32)
    k_gateup<<<gg, 256, GU_SMEM>>>(hs, gate, up);

    dim3 gd(DH / 128, 16, NE);   // (8, 16, 32)
    k_down<<<gd, 256, DN_SMEM>>>(down);

    k_combine<<<NT, 256>>>(out);
}